// round 3
// baseline (speedup 1.0000x reference)
#include <cuda_runtime.h>

#define BSZ 256
#define HSZ 512
#define NSZ 16
#define TSTEPS 63
#define ODIM 9

typedef unsigned long long ull;

// ---------- packed f32x2 helpers (sm_103a FFMA2 path, PTX-only) ----------
__device__ __forceinline__ ull pack2(float lo, float hi) {
    ull r; asm("mov.b64 %0,{%1,%2};" : "=l"(r) : "f"(lo), "f"(hi)); return r;
}
__device__ __forceinline__ float2 unpack2(ull v) {
    float2 r; asm("mov.b64 {%0,%1},%2;" : "=f"(r.x), "=f"(r.y) : "l"(v)); return r;
}
__device__ __forceinline__ ull fma2v(ull a, ull b, ull c) {
    ull d; asm("fma.rn.f32x2 %0,%1,%2,%3;" : "=l"(d) : "l"(a), "l"(b), "l"(c)); return d;
}

__device__ __forceinline__ float gelu_exact(float x) {
    return 0.5f * x * (1.0f + erff(x * 0.70710678118654752440f));
}
__device__ __forceinline__ float sigm(float x) {
    return 1.0f / (1.0f + expf(-x));
}

// ---------- scratch (__device__ globals; no allocation allowed) ----------
__device__ __align__(16) float g_enc[BSZ * 6 * HSZ];          // encoded[:, 0:6, :] only
__device__ __align__(16) float g_states[2 * BSZ * HSZ * NSZ]; // SSM states per layer
__device__ __align__(16) float g_gact[BSZ * HSZ];             // gelu(y) GEMM input
__device__ __align__(16) float g_z[2][BSZ * HSZ];             // pre-LN residual sums
__device__ __align__(16) float g_dp[BSZ * HSZ];               // decoder input proj (step 0)
__device__ __align__(16) float g_ctx[BSZ * HSZ];
__device__ __align__(16) float g_dec[BSZ * 4];
__device__ float g_psum[2][16 * BSZ];                          // per-colblock LN partials
__device__ float g_psumsq[2][16 * BSZ];

// ============================================================
// encoded = input_seq @ in_W + in_b  (only s < 6 ever read: ptr in [0,6))
// ============================================================
__global__ void k_enc(const float* __restrict__ inseq,
                      const float* __restrict__ inW,
                      const float* __restrict__ inb) {
    int idx = blockIdx.x * 256 + threadIdx.x;   // < B*6*H
    int h = idx & (HSZ - 1);
    int bs = idx >> 9;                          // b*6 + s
    int b = bs / 6, s = bs - b * 6;
    const float* r = inseq + (b * 64 + s) * 3;
    g_enc[idx] = fmaf(r[0], inW[h],
                 fmaf(r[1], inW[HSZ + h],
                 fmaf(r[2], inW[2 * HSZ + h], inb[h])));
}

// ============================================================
// zero states / ctx, dec0 = [0,0,1]
// ============================================================
__global__ void k_init() {
    int idx = blockIdx.x * 256 + threadIdx.x;
    if (idx < 2 * BSZ * HSZ * NSZ) g_states[idx] = 0.0f;
    if (idx < BSZ * HSZ) g_ctx[idx] = 0.0f;
    if (idx < BSZ) {
        g_dec[idx * 4 + 0] = 0.0f;
        g_dec[idx * 4 + 1] = 0.0f;
        g_dec[idx * 4 + 2] = 1.0f;
    }
}

// ============================================================
// Decode SSM step. j==0: input = dec @ in_W + in_b (stores dp at step 0).
// j==1: input = LN(z0) via layer-0 LN partial sums.
// Writes g_gact = gelu(y).  grid = B*H/256 blocks of 256.
// ============================================================
__global__ void __launch_bounds__(256)
k_ssm(int isj1, int isstep0, int jbuf,
      const float* __restrict__ Aj, const float* __restrict__ Bj,
      const float* __restrict__ Cj, const float* __restrict__ Dj,
      const float* __restrict__ inW, const float* __restrict__ inb,
      const float* __restrict__ lng, const float* __restrict__ lnb) {
    int idx = blockIdx.x * 256 + threadIdx.x;
    int h = idx & (HSZ - 1);
    int b = idx >> 9;

    float x;
    if (!isj1) {
        float d0 = g_dec[b * 4], d1 = g_dec[b * 4 + 1], d2 = g_dec[b * 4 + 2];
        x = fmaf(d0, inW[h], fmaf(d1, inW[HSZ + h], fmaf(d2, inW[2 * HSZ + h], inb[h])));
        if (isstep0) g_dp[idx] = x;
    } else {
        float s = 0.0f, q = 0.0f;
#pragma unroll
        for (int cb = 0; cb < 16; cb++) {
            s += g_psum[0][cb * BSZ + b];
            q += g_psumsq[0][cb * BSZ + b];
        }
        float m = s * (1.0f / HSZ);
        float rstd = rsqrtf(q * (1.0f / HSZ) - m * m + 1e-5f);
        x = (g_z[0][idx] - m) * rstd * lng[h] + lnb[h];
    }

    const float4* A4 = (const float4*)(Aj + h * NSZ);
    const float4* B4 = (const float4*)(Bj + h * NSZ);
    const float4* C4 = (const float4*)(Cj + h * NSZ);
    float4* S4p = (float4*)(g_states + ((size_t)jbuf * BSZ * HSZ + (size_t)b * HSZ + h) * NSZ);

    float acc = 0.0f;
#pragma unroll
    for (int q4 = 0; q4 < 4; q4++) {
        float4 a = A4[q4], bm = B4[q4], c = C4[q4], s = S4p[q4];
        s.x = fmaf(a.x, s.x, bm.x * x);
        s.y = fmaf(a.y, s.y, bm.y * x);
        s.z = fmaf(a.z, s.z, bm.z * x);
        s.w = fmaf(a.w, s.w, bm.w * x);
        acc += c.x * s.x + c.y * s.y + c.z * s.z + c.w * s.w;
        S4p[q4] = s;
    }
    float y = fmaf(Dj[h], x, acc);
    g_gact[idx] = gelu_exact(y);
}

// ============================================================
// GEMM: y = g_gact(256x512) @ Wj(512x512) + bj; z = step0 ? y+dp : 2y
// writes g_z[jbuf] + per-colblock LN partials (deterministic, no atomics).
// BM=32, BN=32, BK=16, 256 threads, grid (16,8).  f32x2 inner loop.
// ============================================================
__global__ void __launch_bounds__(256)
k_gemm(int jbuf, int isstep0, const float* __restrict__ Wj, const float* __restrict__ bj) {
    __shared__ ull As[16][32];     // A values duplicated (a,a)
    __shared__ float Bs[16][32];
    int t = threadIdx.x;
    int tx = t & 7;                // col group (4 cols)
    int ty = t >> 3;               // row 0..31
    int c0 = blockIdx.x * 32, r0 = blockIdx.y * 32;

    ull acc0 = 0ULL, acc1 = 0ULL;
    int ka = t & 15, ra = t >> 4;  // A tile loader
    int cb = t & 31, kb = t >> 5;  // B tile loader

    for (int k0 = 0; k0 < HSZ; k0 += 16) {
        float a0 = g_gact[(r0 + ra) * HSZ + k0 + ka];
        float a1 = g_gact[(r0 + ra + 16) * HSZ + k0 + ka];
        As[ka][ra] = pack2(a0, a0);
        As[ka][ra + 16] = pack2(a1, a1);
        Bs[kb][cb] = Wj[(k0 + kb) * HSZ + c0 + cb];
        Bs[kb + 8][cb] = Wj[(k0 + kb + 8) * HSZ + c0 + cb];
        __syncthreads();
#pragma unroll
        for (int k = 0; k < 16; k++) {
            ulonglong2 bb = *(ulonglong2*)&Bs[k][tx * 4];
            ull a = As[k][ty];
            acc0 = fma2v(a, bb.x, acc0);
            acc1 = fma2v(a, bb.y, acc1);
        }
        __syncthreads();
    }

    float2 u0 = unpack2(acc0), u1 = unpack2(acc1);
    int row = r0 + ty, c = c0 + tx * 4;
    float4 y4 = make_float4(u0.x + bj[c], u0.y + bj[c + 1],
                            u1.x + bj[c + 2], u1.y + bj[c + 3]);
    float4 z4;
    if (isstep0) {
        float4 dp = *(const float4*)&g_dp[row * HSZ + c];
        z4 = make_float4(y4.x + dp.x, y4.y + dp.y, y4.z + dp.z, y4.w + dp.w);
    } else {
        z4 = make_float4(2.0f * y4.x, 2.0f * y4.y, 2.0f * y4.z, 2.0f * y4.w);
    }
    *(float4*)&g_z[jbuf][row * HSZ + c] = z4;

    float s = z4.x + z4.y + z4.z + z4.w;
    float q = z4.x * z4.x + z4.y * z4.y + z4.z * z4.z + z4.w * z4.w;
#pragma unroll
    for (int d = 1; d < 8; d <<= 1) {
        s += __shfl_xor_sync(0xFFFFFFFFu, s, d);
        q += __shfl_xor_sync(0xFFFFFFFFu, q, d);
    }
    if (tx == 0) {
        g_psum[jbuf][blockIdx.x * BSZ + row] = s;
        g_psumsq[jbuf][blockIdx.x * BSZ + row] = q;
    }
}

// ============================================================
// Head: LN(z1)+ctx, head GEMM (9 warp-dots), argmax pointer retrieval,
// ctx update, output write, next decoder token. 1 block per batch row.
// ============================================================
__global__ void __launch_bounds__(288)
k_head(int step, const float* __restrict__ lng1, const float* __restrict__ lnb1,
       const float* __restrict__ hW, const float* __restrict__ hb,
       float* __restrict__ out) {
    __shared__ float xdc[HSZ];
    __shared__ float part[32];
    __shared__ float gv[ODIM];
    __shared__ float outv[ODIM];
    __shared__ float mv[2];
    __shared__ int ptr_s;

    int b = blockIdx.x;
    int t = threadIdx.x;
    int lane = t & 31, w = t >> 5;

    if (t < 16) part[t] = g_psum[1][t * BSZ + b];
    else if (t < 32) part[t] = g_psumsq[1][(t - 16) * BSZ + b];
    __syncthreads();
    if (t == 0) {
        float s = 0.0f, q = 0.0f;
#pragma unroll
        for (int i = 0; i < 16; i++) { s += part[i]; q += part[16 + i]; }
        float m = s * (1.0f / HSZ);
        mv[0] = m;
        mv[1] = rsqrtf(q * (1.0f / HSZ) - m * m + 1e-5f);
    }
    __syncthreads();
    float m = mv[0], rstd = mv[1];

    if (t < 256) {
#pragma unroll
        for (int rep = 0; rep < 2; rep++) {
            int k = t + rep * 256;
            float xd = (g_z[1][b * HSZ + k] - m) * rstd * lng1[k] + lnb1[k];
            xdc[k] = xd + g_ctx[b * HSZ + k];
        }
    }
    __syncthreads();

    // g1[w] = dot(xd+ctx, head_W[:,w]) + head_b[w]   (9 warps, 16 terms/lane)
    float acc = 0.0f;
#pragma unroll
    for (int qq = 0; qq < 16; qq++) {
        int k = qq * 32 + lane;
        acc = fmaf(xdc[k], hW[k * ODIM + w], acc);
    }
#pragma unroll
    for (int d = 16; d; d >>= 1) acc += __shfl_xor_sync(0xFFFFFFFFu, acc, d);
    if (lane == 0) gv[w] = acc + hb[w];
    __syncthreads();

    bool is_out = ((step & 1) == 0);
    if (is_out) {
        if (t < ODIM) outv[t] = sigm(gv[t]);
        __syncthreads();
        if (t < ODIM) out[b * (TSTEPS * ODIM) + step * ODIM + t] = outv[t];
        if (t == 0) {
            float nc = (outv[0] > 0.5f) ? 1.0f : 0.0f;
            g_dec[b * 4 + 0] = nc;
            g_dec[b * 4 + 1] = 1.0f;
            g_dec[b * 4 + 2] = 0.0f;
        }
    } else {
        if (t == 0) {
            // argmax over sigmoid(gv[3..8]), first-max tie rule (matches jnp)
            float best = sigm(gv[3]); int p = 0;
#pragma unroll
            for (int c = 1; c < 6; c++) {
                float v = sigm(gv[3 + c]);
                if (v > best) { best = v; p = c; }
            }
            ptr_s = p;
        }
        __syncthreads();
        int p = ptr_s;
        const float* ev = g_enc + (b * 6 + p) * HSZ;
        // pv contribution: dot(ptr_vec, head_W[:,w])
        float acc2 = 0.0f;
#pragma unroll
        for (int qq = 0; qq < 16; qq++) {
            int k = qq * 32 + lane;
            acc2 = fmaf(ev[k], hW[k * ODIM + w], acc2);
        }
#pragma unroll
        for (int d = 16; d; d >>= 1) acc2 += __shfl_xor_sync(0xFFFFFFFFu, acc2, d);
        if (lane == 0) outv[w] = sigm(gv[w] + acc2);
        if (t < 256) {
#pragma unroll
            for (int rep = 0; rep < 2; rep++) {
                int k = t + rep * 256;
                g_ctx[b * HSZ + k] += ev[k];
            }
        }
        __syncthreads();
        if (t < ODIM) out[b * (TSTEPS * ODIM) + step * ODIM + t] = outv[t];
        if (t == 0) {
            g_dec[b * 4 + 0] = 0.0f;
            g_dec[b * 4 + 1] = 0.0f;
            g_dec[b * 4 + 2] = 1.0f;
        }
    }
}

// ============================================================
// Launch: 2 setup kernels + 63 steps x 5 kernels = 317 graph nodes
// ============================================================
extern "C" void kernel_launch(void* const* d_in, const int* in_sizes, int n_in,
                              void* d_out, int out_size) {
    // expected order: input_seq, autoregressive_steps(scalar), in_W, in_b, A, Bm,
    // Cm, D, outW, outb, ln_g, ln_b, head_W, head_b.  Handle scalar being dropped.
    int o = (n_in >= 14) ? 1 : 0;
    const float* inseq = (const float*)d_in[0];
    const float* inW = (const float*)d_in[1 + o];
    const float* inb = (const float*)d_in[2 + o];
    const float* A   = (const float*)d_in[3 + o];
    const float* Bm  = (const float*)d_in[4 + o];
    const float* Cm  = (const float*)d_in[5 + o];
    const float* D   = (const float*)d_in[6 + o];
    const float* oW  = (const float*)d_in[7 + o];
    const float* ob  = (const float*)d_in[8 + o];
    const float* lng = (const float*)d_in[9 + o];
    const float* lnb = (const float*)d_in[10 + o];
    const float* hW  = (const float*)d_in[11 + o];
    const float* hb  = (const float*)d_in[12 + o];
    float* out = (float*)d_out;

    k_enc<<<(BSZ * 6 * HSZ) / 256, 256>>>(inseq, inW, inb);
    k_init<<<(2 * BSZ * HSZ * NSZ) / 256, 256>>>();

    dim3 gg(16, 8);   // 16 colblocks x 8 rowblocks
    for (int i = 0; i < TSTEPS; i++) {
        int s0 = (i == 0) ? 1 : 0;
        k_ssm<<<BSZ * HSZ / 256, 256>>>(0, s0, 0, A, Bm, Cm, D, inW, inb, lng, lnb);
        k_gemm<<<gg, 256>>>(0, s0, oW, ob);
        k_ssm<<<BSZ * HSZ / 256, 256>>>(1, s0, 1, A + HSZ * NSZ, Bm + HSZ * NSZ,
                                        Cm + HSZ * NSZ, D + HSZ, inW, inb, lng, lnb);
        k_gemm<<<gg, 256>>>(1, s0, oW + HSZ * HSZ, ob + HSZ);
        k_head<<<BSZ, 288>>>(i, lng + HSZ, lnb + HSZ, hW, hb, out);
    }
}

// round 4
// speedup vs baseline: 2.4039x; 2.4039x over previous
#include <cuda_runtime.h>

#define BSZ 256
#define HSZ 512
#define NSZ 16
#define TSTEPS 63
#define ODIM 9
#define KC 8            // split-K chunks
#define KCH 64          // K per chunk

typedef unsigned long long ull;

// ---------- packed f32x2 helpers (sm_103a FFMA2 path, PTX-only) ----------
__device__ __forceinline__ ull pack2(float lo, float hi) {
    ull r; asm("mov.b64 %0,{%1,%2};" : "=l"(r) : "f"(lo), "f"(hi)); return r;
}
__device__ __forceinline__ float2 unpack2(ull v) {
    float2 r; asm("mov.b64 {%0,%1},%2;" : "=f"(r.x), "=f"(r.y) : "l"(v)); return r;
}
__device__ __forceinline__ ull fma2v(ull a, ull b, ull c) {
    ull d; asm("fma.rn.f32x2 %0,%1,%2,%3;" : "=l"(d) : "l"(a), "l"(b), "l"(c)); return d;
}

__device__ __forceinline__ float gelu_exact(float x) {
    return 0.5f * x * (1.0f + erff(x * 0.70710678118654752440f));
}
__device__ __forceinline__ float sigm(float x) {
    return 1.0f / (1.0f + expf(-x));
}

// ---------- scratch (__device__ globals; no allocation allowed) ----------
__device__ __align__(16) float g_enc[BSZ * 6 * HSZ];          // encoded[:, 0:6, :] only
__device__ __align__(16) float g_states[2 * BSZ * HSZ * NSZ]; // SSM states per layer
__device__ __align__(16) float g_gact[BSZ * HSZ];             // gelu(y) GEMM input
__device__ __align__(16) float g_dp[BSZ * HSZ];               // decoder proj (step 0)
__device__ __align__(16) float g_ctx[BSZ * HSZ];
__device__ __align__(16) float g_part[KC * BSZ * HSZ];        // split-K GEMM partials

// ============================================================
// encoded = input_seq @ in_W + in_b  (only s < 6 ever read: ptr in [0,6))
// ============================================================
__global__ void k_enc(const float* __restrict__ inseq,
                      const float* __restrict__ inW,
                      const float* __restrict__ inb) {
    int idx = blockIdx.x * 256 + threadIdx.x;   // < B*6*H
    int h = idx & (HSZ - 1);
    int bs = idx >> 9;                          // b*6 + s
    int b = bs / 6, s = bs - b * 6;
    const float* r = inseq + (b * 64 + s) * 3;
    g_enc[idx] = fmaf(r[0], inW[h],
                 fmaf(r[1], inW[HSZ + h],
                 fmaf(r[2], inW[2 * HSZ + h], inb[h])));
}

// ============================================================
// zero states / ctx
// ============================================================
__global__ void k_init() {
    int idx = blockIdx.x * 256 + threadIdx.x;
    if (idx < 2 * BSZ * HSZ * NSZ) g_states[idx] = 0.0f;
    if (idx < BSZ * HSZ) g_ctx[idx] = 0.0f;
}

// ============================================================
// Step-0 decoder proj + layer-0 SSM (dec0 = [0,0,1], states = 0)
// ============================================================
__global__ void __launch_bounds__(256)
k_first(const float* __restrict__ inW, const float* __restrict__ inb,
        const float* __restrict__ A0, const float* __restrict__ B0,
        const float* __restrict__ C0, const float* __restrict__ D0) {
    int idx = blockIdx.x * 256 + threadIdx.x;   // < B*H
    int h = idx & (HSZ - 1);
    int b = idx >> 9;
    float x = inW[2 * HSZ + h] + inb[h];
    g_dp[idx] = x;

    const float4* B4 = (const float4*)(B0 + h * NSZ);
    const float4* C4 = (const float4*)(C0 + h * NSZ);
    float4* S4p = (float4*)(g_states + ((size_t)b * HSZ + h) * NSZ);
    float acc = 0.0f;
#pragma unroll
    for (int q = 0; q < 4; q++) {
        float4 bm = B4[q], c = C4[q];
        float4 s = make_float4(bm.x * x, bm.y * x, bm.z * x, bm.w * x);
        acc += c.x * s.x + c.y * s.y + c.z * s.z + c.w * s.w;
        S4p[q] = s;
    }
    g_gact[idx] = gelu_exact(fmaf(D0[h], x, acc));
}

// ============================================================
// Split-K GEMM: g_part[z] += g_gact(256x512) @ W chunk z (no bias here)
// grid (4 ncb, 8 mrb, 8 kc), 128 threads. Block tile 32x128, chunk 64.
// Thread tile 8 rows x 4 cols, row-pair f32x2. One __syncthreads total.
// ============================================================
__global__ void __launch_bounds__(128)
k_gemm(const float* __restrict__ W) {
    __shared__ float As[KCH][34];     // transposed: As[k][r], pad keeps 8B align
    __shared__ float Bs[KCH][128];
    int t = threadIdx.x, lane = t & 31, w = t >> 5;
    int n0 = blockIdx.x * 128, m0 = blockIdx.y * 32, k0 = blockIdx.z * KCH;

    // stage A: 32 rows x 64 k, transposed
    {
        int kk = (t & 15) * 4, rr = t >> 4;     // rr 0..7
#pragma unroll
        for (int p = 0; p < 4; p++) {
            float4 v = *(const float4*)&g_gact[(m0 + rr + 8 * p) * HSZ + k0 + kk];
            As[kk + 0][rr + 8 * p] = v.x;
            As[kk + 1][rr + 8 * p] = v.y;
            As[kk + 2][rr + 8 * p] = v.z;
            As[kk + 3][rr + 8 * p] = v.w;
        }
    }
    // stage B: 64 k x 128 cols
    {
        int cc = (t & 31) * 4, kk = t >> 5;     // kk 0..3
#pragma unroll
        for (int p = 0; p < 16; p++)
            *(float4*)&Bs[kk + 4 * p][cc] = *(const float4*)&W[(k0 + kk + 4 * p) * HSZ + n0 + cc];
    }
    __syncthreads();

    ull acc[4][4];
#pragma unroll
    for (int i = 0; i < 4; i++)
#pragma unroll
        for (int j = 0; j < 4; j++) acc[i][j] = 0ULL;

    int rbase = w * 8;        // warp rows [m0+8w, m0+8w+8)
    int cbase = lane * 4;     // lane cols [n0+4l, n0+4l+4)

#pragma unroll 8
    for (int k = 0; k < KCH; k++) {
        float4 bv = *(const float4*)&Bs[k][cbase];
        ull b0 = pack2(bv.x, bv.x), b1 = pack2(bv.y, bv.y);
        ull b2 = pack2(bv.z, bv.z), b3 = pack2(bv.w, bv.w);
#pragma unroll
        for (int rp = 0; rp < 4; rp++) {
            ull av = *(const ull*)&As[k][rbase + rp * 2];   // broadcast (r, r+1)
            acc[rp][0] = fma2v(av, b0, acc[rp][0]);
            acc[rp][1] = fma2v(av, b1, acc[rp][1]);
            acc[rp][2] = fma2v(av, b2, acc[rp][2]);
            acc[rp][3] = fma2v(av, b3, acc[rp][3]);
        }
    }

    float* P = g_part + (size_t)blockIdx.z * BSZ * HSZ;
#pragma unroll
    for (int rp = 0; rp < 4; rp++) {
        int row = m0 + rbase + rp * 2;
#pragma unroll
        for (int c = 0; c < 4; c++) {
            float2 v = unpack2(acc[rp][c]);
            int col = n0 + cbase + c;
            P[row * HSZ + col] = v.x;
            P[(row + 1) * HSZ + col] = v.y;
        }
    }
}

// ---------- deterministic block LN over 512 threads ----------
__device__ __forceinline__ void blk_ln(float z, int t, int lane, int w,
                                       float* red, float& m, float& rstd) {
    float s = z, q = z * z;
#pragma unroll
    for (int d = 16; d; d >>= 1) {
        s += __shfl_xor_sync(0xFFFFFFFFu, s, d);
        q += __shfl_xor_sync(0xFFFFFFFFu, q, d);
    }
    if (lane == 0) { red[w] = s; red[16 + w] = q; }
    __syncthreads();
    if (t == 0) {
        float ss = 0.0f, qq = 0.0f;
#pragma unroll
        for (int i = 0; i < 16; i++) { ss += red[i]; qq += red[16 + i]; }
        float mm = ss * (1.0f / HSZ);
        red[32] = mm;
        red[33] = rsqrtf(qq * (1.0f / HSZ) - mm * mm + 1e-5f);
    }
    __syncthreads();
    m = red[32]; rstd = red[33];
}

// ============================================================
// ssm1: z0 = sum(partials)+bias (+residual), LN -> x, layer-1 SSM -> g_gact
// block per batch row, 512 threads (t = h)
// ============================================================
__global__ void __launch_bounds__(512)
k_ssm1(int isstep0,
       const float* __restrict__ ob0, const float* __restrict__ lng0,
       const float* __restrict__ lnb0,
       const float* __restrict__ A1, const float* __restrict__ B1,
       const float* __restrict__ C1, const float* __restrict__ D1) {
    __shared__ float red[34];
    int b = blockIdx.x, t = threadIdx.x;
    int lane = t & 31, w = t >> 5;

    float y = 0.0f;
#pragma unroll
    for (int z = 0; z < KC; z++) y += g_part[((size_t)z * BSZ + b) * HSZ + t];
    y += ob0[t];
    float zz = isstep0 ? (y + g_dp[b * HSZ + t]) : (2.0f * y);

    float m, rstd;
    blk_ln(zz, t, lane, w, red, m, rstd);
    float x = (zz - m) * rstd * lng0[t] + lnb0[t];

    const float4* A4 = (const float4*)(A1 + t * NSZ);
    const float4* B4 = (const float4*)(B1 + t * NSZ);
    const float4* C4 = (const float4*)(C1 + t * NSZ);
    float4* S4p = (float4*)(g_states + ((size_t)BSZ * HSZ + (size_t)b * HSZ + t) * NSZ);
    float acc = 0.0f;
#pragma unroll
    for (int q = 0; q < 4; q++) {
        float4 a = A4[q], bm = B4[q], c = C4[q], s = S4p[q];
        s.x = fmaf(a.x, s.x, bm.x * x);
        s.y = fmaf(a.y, s.y, bm.y * x);
        s.z = fmaf(a.z, s.z, bm.z * x);
        s.w = fmaf(a.w, s.w, bm.w * x);
        acc += c.x * s.x + c.y * s.y + c.z * s.z + c.w * s.w;
        S4p[q] = s;
    }
    g_gact[b * HSZ + t] = gelu_exact(fmaf(D1[t], x, acc));
}

// ============================================================
// head (+ fused next-step decoder proj & layer-0 SSM)
// block per batch row, 512 threads
// ============================================================
__global__ void __launch_bounds__(512)
k_head(int step,
       const float* __restrict__ ob1, const float* __restrict__ lng1,
       const float* __restrict__ lnb1,
       const float* __restrict__ hW, const float* __restrict__ hb,
       const float* __restrict__ inW, const float* __restrict__ inb,
       const float* __restrict__ A0, const float* __restrict__ B0,
       const float* __restrict__ C0, const float* __restrict__ D0,
       float* __restrict__ out) {
    __shared__ float xdc[HSZ];
    __shared__ float red[34];
    __shared__ float gv[12];
    __shared__ float decs[3];
    __shared__ int ptr_s;

    int b = blockIdx.x, t = threadIdx.x;
    int lane = t & 31, w = t >> 5;

    // z1 from split-K partials
    float y = 0.0f;
#pragma unroll
    for (int z = 0; z < KC; z++) y += g_part[((size_t)z * BSZ + b) * HSZ + t];
    y += ob1[t];
    float zz = (step == 0) ? (y + g_dp[b * HSZ + t]) : (2.0f * y);

    float m, rstd;
    blk_ln(zz, t, lane, w, red, m, rstd);
    float xd = (zz - m) * rstd * lng1[t] + lnb1[t];
    float ctxv = g_ctx[b * HSZ + t];
    xdc[t] = xd + ctxv;
    __syncthreads();

    // head logits: warp w (<9) computes dot(xdc, head_W[:,w]) + head_b[w]
    if (w < ODIM) {
        float a = 0.0f;
#pragma unroll
        for (int q = 0; q < 16; q++) {
            int k = q * 32 + lane;
            a = fmaf(xdc[k], hW[k * ODIM + w], a);
        }
#pragma unroll
        for (int d = 16; d; d >>= 1) a += __shfl_xor_sync(0xFFFFFFFFu, a, d);
        if (lane == 0) gv[w] = a + hb[w];
    }
    __syncthreads();

    bool is_out = ((step & 1) == 0);
    if (is_out) {
        if (t < ODIM) out[b * (TSTEPS * ODIM) + step * ODIM + t] = sigm(gv[t]);
        if (t == 0) {
            decs[0] = (sigm(gv[0]) > 0.5f) ? 1.0f : 0.0f;
            decs[1] = 1.0f; decs[2] = 0.0f;
        }
    } else {
        if (t == 0) {
            float best = sigm(gv[3]); int p = 0;
#pragma unroll
            for (int c = 1; c < 6; c++) {
                float v = sigm(gv[3 + c]);
                if (v > best) { best = v; p = c; }
            }
            ptr_s = p;
            decs[0] = 0.0f; decs[1] = 0.0f; decs[2] = 1.0f;
        }
        __syncthreads();                       // uniform branch: safe
        const float* ev = g_enc + (b * 6 + ptr_s) * HSZ;
        g_ctx[b * HSZ + t] = ctxv + ev[t];     // ctx += ptr_vec
        if (w < ODIM) {
            float a2 = 0.0f;
#pragma unroll
            for (int q = 0; q < 16; q++) {
                int k = q * 32 + lane;
                a2 = fmaf(ev[k], hW[k * ODIM + w], a2);
            }
#pragma unroll
            for (int d = 16; d; d >>= 1) a2 += __shfl_xor_sync(0xFFFFFFFFu, a2, d);
            if (lane == 0)
                out[b * (TSTEPS * ODIM) + step * ODIM + w] = sigm(gv[w] + a2);
        }
    }
    __syncthreads();

    // fused next-step: decoder proj + layer-0 SSM (harmless on last step)
    float d0 = decs[0], d1 = decs[1], d2 = decs[2];
    float x = fmaf(d0, inW[t], fmaf(d1, inW[HSZ + t], fmaf(d2, inW[2 * HSZ + t], inb[t])));

    const float4* A4 = (const float4*)(A0 + t * NSZ);
    const float4* B4 = (const float4*)(B0 + t * NSZ);
    const float4* C4 = (const float4*)(C0 + t * NSZ);
    float4* S4p = (float4*)(g_states + ((size_t)b * HSZ + t) * NSZ);
    float acc = 0.0f;
#pragma unroll
    for (int q = 0; q < 4; q++) {
        float4 a = A4[q], bm = B4[q], c = C4[q], s = S4p[q];
        s.x = fmaf(a.x, s.x, bm.x * x);
        s.y = fmaf(a.y, s.y, bm.y * x);
        s.z = fmaf(a.z, s.z, bm.z * x);
        s.w = fmaf(a.w, s.w, bm.w * x);
        acc += c.x * s.x + c.y * s.y + c.z * s.z + c.w * s.w;
        S4p[q] = s;
    }
    g_gact[b * HSZ + t] = gelu_exact(fmaf(D0[t], x, acc));
}

// ============================================================
// Launch: 3 setup + 63 x 4 = 255 graph nodes
// ============================================================
extern "C" void kernel_launch(void* const* d_in, const int* in_sizes, int n_in,
                              void* d_out, int out_size) {
    int o = (n_in >= 14) ? 1 : 0;   // skip scalar autoregressive_steps if present
    const float* inseq = (const float*)d_in[0];
    const float* inW = (const float*)d_in[1 + o];
    const float* inb = (const float*)d_in[2 + o];
    const float* A   = (const float*)d_in[3 + o];
    const float* Bm  = (const float*)d_in[4 + o];
    const float* Cm  = (const float*)d_in[5 + o];
    const float* D   = (const float*)d_in[6 + o];
    const float* oW  = (const float*)d_in[7 + o];
    const float* ob  = (const float*)d_in[8 + o];
    const float* lng = (const float*)d_in[9 + o];
    const float* lnb = (const float*)d_in[10 + o];
    const float* hW  = (const float*)d_in[11 + o];
    const float* hb  = (const float*)d_in[12 + o];
    float* out = (float*)d_out;

    const float *A1 = A + HSZ * NSZ, *B1 = Bm + HSZ * NSZ, *C1 = Cm + HSZ * NSZ, *D1 = D + HSZ;
    const float *oW1 = oW + HSZ * HSZ, *ob1 = ob + HSZ;
    const float *lng1 = lng + HSZ, *lnb1 = lnb + HSZ;

    k_enc<<<(BSZ * 6 * HSZ) / 256, 256>>>(inseq, inW, inb);
    k_init<<<(2 * BSZ * HSZ * NSZ) / 256, 256>>>();
    k_first<<<(BSZ * HSZ) / 256, 256>>>(inW, inb, A, Bm, Cm, D);

    dim3 gg(4, 8, KC);   // 4 colblocks x 8 rowblocks x 8 K-chunks = 256 blocks
    for (int i = 0; i < TSTEPS; i++) {
        int s0 = (i == 0) ? 1 : 0;
        k_gemm<<<gg, 128>>>(oW);                                    // layer 0 GEMM
        k_ssm1<<<BSZ, 512>>>(s0, ob, lng, lnb, A1, B1, C1, D1);     // +LN0, layer-1 SSM
        k_gemm<<<gg, 128>>>(oW1);                                   // layer 1 GEMM
        k_head<<<BSZ, 512>>>(i, ob1, lng1, lnb1, hW, hb,
                             inW, inb, A, Bm, Cm, D, out);          // +LN1, head, next ssm0
    }
}